// round 5
// baseline (speedup 1.0000x reference)
#include <cuda_runtime.h>

#define BB 256
#define SS 2048
#define VOCAB 10
#define EE 32
#define HH 64
#define OUTD 10
#define HSTRIDE 68   // 272B rows: 16B-aligned, spreads banks for epilogue

typedef unsigned long long ull;

// ---- packed f32x2 helpers (sm_103a) ----
__device__ __forceinline__ ull pk2(float lo, float hi) {
    ull r;
    asm("mov.b64 %0, {%1, %2};" : "=l"(r) : "f"(lo), "f"(hi));
    return r;
}
__device__ __forceinline__ void fma2(ull& acc, ull a, ull b) {
    asm("fma.rn.f32x2 %0, %1, %2, %0;" : "+l"(acc) : "l"(a), "l"(b));
}
__device__ __forceinline__ ull add2(ull a, ull b) {
    ull r;
    asm("add.rn.f32x2 %0, %1, %2;" : "=l"(r) : "l"(a), "l"(b));
    return r;
}
__device__ __forceinline__ float2 unpk2(ull x) {
    float lo, hi;
    asm("mov.b64 {%0, %1}, %2;" : "=f"(lo), "=f"(hi) : "l"(x));
    return make_float2(lo, hi);
}
// tanh = 1 - 2/(exp(2z)+1) via EX2 + RCP (rel err ~1e-7)
__device__ __forceinline__ float fast_tanh(float z) {
    float t = z * 2.885390081777927f;  // 2*log2(e)
    float e; asm("ex2.approx.f32 %0, %1;" : "=f"(e) : "f"(t));
    float r; asm("rcp.approx.f32 %0, %1;" : "=f"(r) : "f"(e + 1.0f));
    return fmaf(-2.0f, r, 1.0f);
}

__global__ __launch_bounds__(128, 1) void rnn_pipe_kernel(
    const int* __restrict__ num1, const int* __restrict__ num2,
    const float* __restrict__ embed, const float* __restrict__ Wx,
    const float* __restrict__ Wh, const float* __restrict__ b,
    const float* __restrict__ Wd, const float* __restrict__ bd,
    float* __restrict__ out)
{
    __shared__ float t1f[VOCAB][HH];                       // input-proj tables
    __shared__ float t2f[VOCAB][HH];
    __shared__ unsigned char idx[2][SS];                   // nibble-packed tokens
    __shared__ __align__(16) float hist[2][64][HSTRIDE];   // rotating h history
    __shared__ __align__(8)  float wdkT[OUTD][HH];         // Wd transposed [o][k]
    __shared__ float bd_sh[OUTD];

    const int tid  = threadIdx.x;     // 0..127
    const int rowL = tid >> 6;        // warps 0,1 -> row A ; warps 2,3 -> row B
    const int c    = tid & 63;        // hidden column owned by this thread
    const int r0   = blockIdx.x * 2;

    // ---- Prologue ----
    if (tid < HH) {   // input-projection tables (10+10 distinct halves)
        const int jj = tid;
        float wxa[EE], wxb[EE];
        #pragma unroll
        for (int e = 0; e < EE; e++) {
            wxa[e] = Wx[e * HH + jj];
            wxb[e] = Wx[(EE + e) * HH + jj];
        }
        float bj = b[jj];
        #pragma unroll
        for (int v = 0; v < VOCAB; v++) {
            float a1 = bj, a2 = 0.0f;
            #pragma unroll
            for (int e = 0; e < EE; e++) {
                float ev = embed[v * EE + e];
                a1 = fmaf(ev, wxa[e], a1);
                a2 = fmaf(ev, wxb[e], a2);
            }
            t1f[v][jj] = a1;
            t2f[v][jj] = a2;
        }
    }
    // Wd transposed + bias
    for (int i = tid; i < HH * OUTD; i += 128) wdkT[i % OUTD][i / OUTD] = Wd[i];
    if (tid < OUTD) bd_sh[tid] = bd[tid];
    // token indices, nibble-packed, both rows
    {
        const int* n1A = num1 + (size_t)r0 * SS;
        const int* n2A = num2 + (size_t)r0 * SS;
        for (int i = tid; i < SS; i += 128) {
            idx[0][i] = (unsigned char)(n1A[i] | (n2A[i] << 4));
            idx[1][i] = (unsigned char)(n1A[SS + i] | (n2A[SS + i] << 4));
        }
    }
    // Wh column c as 32 packed k-pairs (coalesced across threads)
    ull w[HH / 2];
    #pragma unroll
    for (int m = 0; m < HH / 2; m++)
        w[m] = pk2(Wh[(2 * m) * HH + c], Wh[(2 * m + 1) * HH + c]);

    hist[rowL][63][c] = 0.0f;   // h_{-1} = 0 (step s reads slot (s+63)&63)
    __syncthreads();

    float* outrow = out + (size_t)(r0 + rowL) * SS * OUTD;

    // software-pipelined input lookup for step 0
    int   pknext  = idx[rowL][0];
    float t12next = t1f[pknext & 15][c] + t2f[pknext >> 4][c];

    #pragma unroll 4
    for (int s = 0; s < SS; s++) {
        // accumulators seeded with this step's input projection (off-chain)
        ull a0 = pk2(t12next, 0.0f);
        ull a1 = 0ull, a2 = 0ull, a3 = 0ull;

        const ulonglong2* hv = (const ulonglong2*)hist[rowL][(s + 63) & 63];
        #pragma unroll
        for (int m = 0; m < 8; m++) {   // 16B broadcast loads; 32 FMA2 total
            ulonglong2 hh0 = hv[2 * m];
            fma2(a0, hh0.x, w[4 * m + 0]);
            fma2(a1, hh0.y, w[4 * m + 1]);
            ulonglong2 hh1 = hv[2 * m + 1];
            fma2(a2, hh1.x, w[4 * m + 2]);
            fma2(a3, hh1.y, w[4 * m + 3]);
        }

        // prefetch next step's input projection while FMA chain drains
        if (s + 1 < SS) {
            int pk2n = idx[rowL][s + 1];
            t12next = t1f[pk2n & 15][c] + t2f[pk2n >> 4][c];
        }

        float2 u = unpk2(add2(add2(a0, a1), add2(a2, a3)));
        float hn = fast_tanh(u.x + u.y);
        hist[rowL][s & 63][c] = hn;       // conflict-free: bank = c%32
        __syncthreads();                  // cheap HW barrier (floor ~7 cyc)

        if ((s & 63) == 63) {
            // ---- Fused output projection: thread c handles local step c ----
            const ull* hp = (const ull*)hist[rowL][c];
            ull oacc[OUTD];
            #pragma unroll
            for (int o = 0; o < OUTD; o++) oacc[o] = 0ull;
            #pragma unroll
            for (int k2 = 0; k2 < HH / 2; k2++) {
                ull hvv = hp[k2];
                #pragma unroll
                for (int o = 0; o < OUTD; o++)
                    fma2(oacc[o], hvv, *((const ull*)wdkT[o] + k2));
            }
            float* op = outrow + (size_t)(s - 63 + c) * OUTD;
            float2* op2 = (float2*)op;    // 40B rows -> 8B aligned
            #pragma unroll
            for (int o = 0; o < OUTD / 2; o++) {
                float2 ua = unpk2(oacc[2 * o]);
                float2 ub = unpk2(oacc[2 * o + 1]);
                op2[o] = make_float2(ua.x + ua.y + bd_sh[2 * o],
                                     ub.x + ub.y + bd_sh[2 * o + 1]);
            }
            __syncthreads();  // epilogue reads done before slots overwritten
        }
    }
}

extern "C" void kernel_launch(void* const* d_in, const int* in_sizes, int n_in,
                              void* d_out, int out_size)
{
    (void)in_sizes; (void)n_in; (void)out_size;
    const int*   num1  = (const int*)d_in[0];
    const int*   num2  = (const int*)d_in[1];
    const float* embed = (const float*)d_in[2];
    const float* Wx    = (const float*)d_in[3];
    const float* Wh    = (const float*)d_in[4];
    const float* b     = (const float*)d_in[5];
    const float* Wd    = (const float*)d_in[6];
    const float* bd    = (const float*)d_in[7];
    float* out = (float*)d_out;

    rnn_pipe_kernel<<<BB / 2, 128>>>(num1, num2, embed, Wx, Wh, b, Wd, bd, out);
}